// round 4
// baseline (speedup 1.0000x reference)
#include <cuda_runtime.h>
#include <math.h>
#include <stdint.h>

#define N_PTS 65536
#define DIMS  64
#define KCL   128
#define ABLK  128                 // points per assign/scatter block
#define NBLK  (N_PTS / ABLK)      // 512
#define KD    (KCL * DIMS)        // 8192
#define EPSV  1e-8f
#define BIGF  3.402823466e38f
#define PMAX_SMEM 16384           // max P sorted in shared (64KB)

// ----------------------------------------------------------------------------
// Device scratch (static, no allocation)
// ----------------------------------------------------------------------------
__device__ int    g_pred[N_PTS];
__device__ int    g_histx[NBLK * KCL];
__device__ int    g_histt[NBLK * KCL];
__device__ float  g_fill[KCL];
__device__ int    g_m[KCL];
__device__ int    g_P[KCL];
__device__ int    g_off[KCL];
__device__ double g_loss[2];   // [0] = loss_fil, [1] = loss_med
__device__ float  g_xg[(size_t)(2 * N_PTS) * DIMS];
__device__ float  g_tg[(size_t)(2 * N_PTS) * DIMS];

// ----------------------------------------------------------------------------
// K0: zero accumulators
// ----------------------------------------------------------------------------
__global__ void k_init() {
    int t = threadIdx.x;
    if (t < KCL) g_fill[t] = 0.0f;
    if (t < 2)   g_loss[t] = 0.0;
}

// ----------------------------------------------------------------------------
// K1: distances to 128 centers, argmin, soft filling (single distance pass via
//     shared w-cache), per-block histograms for both x-pred and t-pred.
// ----------------------------------------------------------------------------
__global__ void k_assign(const float* __restrict__ x, const float* __restrict__ cc,
                         const int* __restrict__ predt) {
    extern __shared__ float dyn[];
    float* sc    = dyn;                      // 8192
    float* scn   = sc + KCL * DIMS;          // 128
    float* wca   = scn + KCL;                // 16384
    float* sfill = wca + KCL * ABLK;         // 128
    int*   shx   = (int*)(sfill + KCL);      // 128
    int*   sht   = shx + KCL;                // 128

    const int tid = threadIdx.x;

    for (int j = tid; j < KCL * DIMS; j += ABLK) sc[j] = cc[j];
    if (tid < KCL) { sfill[tid] = 0.0f; shx[tid] = 0; sht[tid] = 0; }
    __syncthreads();
    if (tid < KCL) {
        float s = 0.0f;
        const float* cp = sc + tid * DIMS;
        #pragma unroll
        for (int d = 0; d < DIMS; d++) s += cp[d] * cp[d];
        scn[tid] = s;
    }
    __syncthreads();

    const int i = blockIdx.x * ABLK + tid;
    float xr[DIMS];
    {
        const float4* xp = (const float4*)(x + (size_t)i * DIMS);
        #pragma unroll
        for (int q = 0; q < 16; q++) {
            float4 v = xp[q];
            xr[4*q] = v.x; xr[4*q+1] = v.y; xr[4*q+2] = v.z; xr[4*q+3] = v.w;
        }
    }
    float xn = 0.0f;
    #pragma unroll
    for (int d = 0; d < DIMS; d++) xn += xr[d] * xr[d];

    float wsum = 0.0f, best = BIGF;
    int bc = 0;
    for (int c = 0; c < KCL; c++) {
        const float4* cp = (const float4*)(sc + c * DIMS);
        float a0 = 0.f, a1 = 0.f, a2 = 0.f, a3 = 0.f;
        #pragma unroll
        for (int q = 0; q < 16; q++) {
            float4 v = cp[q];
            a0 += xr[4*q]   * v.x;
            a1 += xr[4*q+1] * v.y;
            a2 += xr[4*q+2] * v.z;
            a3 += xr[4*q+3] * v.w;
        }
        float dot = (a0 + a1) + (a2 + a3);
        float d2 = xn + scn[c] - 2.0f * dot;
        float dist = sqrtf(fmaxf(d2, 0.0f));
        if (dist < best) { best = dist; bc = c; }
        float w = __fdividef(1.0f, dist + EPSV);
        wca[c * ABLK + tid] = w;
        wsum += w;
    }
    const float inv = __fdividef(1.0f, wsum);
    const int lane = tid & 31;

    for (int c = 0; c < KCL; c++) {
        float w = wca[c * ABLK + tid] * inv;
        #pragma unroll
        for (int o = 16; o > 0; o >>= 1) w += __shfl_down_sync(0xffffffffu, w, o);
        if (lane == 0) atomicAdd(&sfill[c], w);
    }

    g_pred[i] = bc;
    atomicAdd(&shx[bc], 1);
    atomicAdd(&sht[predt[i]], 1);
    __syncthreads();
    if (tid < KCL) {
        atomicAdd(&g_fill[tid], sfill[tid]);
        g_histx[blockIdx.x * KCL + tid] = shx[tid];
        g_histt[blockIdx.x * KCL + tid] = sht[tid];
    }
}

// ----------------------------------------------------------------------------
// K2a: per-cluster exclusive scan of block histograms (128 blocks x 512 thr)
// ----------------------------------------------------------------------------
__global__ void k_scan1() {
    const int c = blockIdx.x;
    const int t = threadIdx.x;
    __shared__ int s[NBLK];

    int v = g_histx[t * KCL + c];
    s[t] = v; __syncthreads();
    int acc = v;
    for (int o = 1; o < NBLK; o <<= 1) {
        int add = (t >= o) ? s[t - o] : 0;
        __syncthreads();
        acc += add; s[t] = acc;
        __syncthreads();
    }
    g_histx[t * KCL + c] = acc - v;
    int cntx = s[NBLK - 1];
    __syncthreads();

    v = g_histt[t * KCL + c];
    s[t] = v; __syncthreads();
    acc = v;
    for (int o = 1; o < NBLK; o <<= 1) {
        int add = (t >= o) ? s[t - o] : 0;
        __syncthreads();
        acc += add; s[t] = acc;
        __syncthreads();
    }
    g_histt[t * KCL + c] = acc - v;
    int cntt = s[NBLK - 1];

    if (t == 0) {
        int m = min(cntx, cntt);
        g_m[c] = m;
        int P = 0;
        if (m > 0) { P = 1; while (P < m) P <<= 1; }
        g_P[c] = P;
    }
}

// ----------------------------------------------------------------------------
// K2b: offsets across clusters + loss_fil
// ----------------------------------------------------------------------------
__global__ void k_scan2(const float* __restrict__ ftgt) {
    const int c = threadIdx.x;
    __shared__ int sp[KCL];
    __shared__ float sd[KCL];
    sp[c] = g_P[c];
    float diff = g_fill[c] * (1.0f / N_PTS) - ftgt[c];
    sd[c] = diff * diff;
    __syncthreads();
    if (c == 0) {
        int acc = 0;
        for (int k = 0; k < KCL; k++) { g_off[k] = acc; acc += sp[k]; }
        float s = 0.0f;
        for (int k = 0; k < KCL; k++) s += sd[k];
        g_loss[0] = (double)(s / KCL);
    }
}

// ----------------------------------------------------------------------------
// K3: stable rank + gather, BOTH sides in one kernel (fewer launches).
// ----------------------------------------------------------------------------
__global__ void k_scatter2(const float* __restrict__ x, const float* __restrict__ tgt,
                           const int* __restrict__ predt) {
    __shared__ int cntx[KCL];
    __shared__ int cntt[KCL];
    const int tid = threadIdx.x;
    if (tid < KCL) { cntx[tid] = 0; cntt[tid] = 0; }
    __syncthreads();

    const int i = blockIdx.x * ABLK + tid;
    const int cx = g_pred[i];
    const int ct = predt[i];
    const int myw = tid >> 5, lane = tid & 31;
    int rx = 0, rt = 0;

    for (int w = 0; w < ABLK / 32; w++) {
        if (myw == w) {
            unsigned peers = __match_any_sync(0xffffffffu, cx);
            unsigned lower = peers & ((1u << lane) - 1u);
            int leader = __ffs(peers) - 1;
            int base = 0;
            if (lane == leader) base = atomicAdd(&cntx[cx], __popc(peers));
            base = __shfl_sync(0xffffffffu, base, leader);
            rx = base + __popc(lower);

            peers = __match_any_sync(0xffffffffu, ct);
            lower = peers & ((1u << lane) - 1u);
            leader = __ffs(peers) - 1;
            base = 0;
            if (lane == leader) base = atomicAdd(&cntt[ct], __popc(peers));
            base = __shfl_sync(0xffffffffu, base, leader);
            rt = base + __popc(lower);
        }
        __syncthreads();
    }

    // side x
    {
        const int r = g_histx[blockIdx.x * KCL + cx] + rx;
        if (r < g_m[cx]) {
            const int P = g_P[cx];
            float* dst = g_xg + (size_t)g_off[cx] * DIMS + r;
            const float4* sp = (const float4*)(x + (size_t)i * DIMS);
            #pragma unroll
            for (int q = 0; q < 16; q++) {
                float4 v = sp[q];
                dst[(size_t)(4*q)     * P] = v.x;
                dst[(size_t)(4*q + 1) * P] = v.y;
                dst[(size_t)(4*q + 2) * P] = v.z;
                dst[(size_t)(4*q + 3) * P] = v.w;
            }
        }
    }
    // side t
    {
        const int r = g_histt[blockIdx.x * KCL + ct] + rt;
        if (r < g_m[ct]) {
            const int P = g_P[ct];
            float* dst = g_tg + (size_t)g_off[ct] * DIMS + r;
            const float4* sp = (const float4*)(tgt + (size_t)i * DIMS);
            #pragma unroll
            for (int q = 0; q < 16; q++) {
                float4 v = sp[q];
                dst[(size_t)(4*q)     * P] = v.x;
                dst[(size_t)(4*q + 1) * P] = v.y;
                dst[(size_t)(4*q + 2) * P] = v.z;
                dst[(size_t)(4*q + 3) * P] = v.w;
            }
        }
    }
}

// ----------------------------------------------------------------------------
// K4: grid-stride register/shfl-blocked bitonic sort over ALL 2*KD segments.
//     One kernel, no empty-block waves; 256 thr, 64KB smem (3 CTAs/SM).
//     Handles P <= PMAX_SMEM.
// ----------------------------------------------------------------------------
#define SORT_T 256
#define SORT_VC 8
__global__ void __launch_bounds__(SORT_T)
k_sort_ws() {
    extern __shared__ float sh[];
    const int tid = threadIdx.x;

    for (int s = blockIdx.x; s < 2 * KD; s += gridDim.x) {
        float* buf = (s < KD) ? g_xg : g_tg;
        const int cd = (s < KD) ? s : s - KD;
        const int c = cd >> 6, d = cd & 63;
        const int m = g_m[c];
        if (m < 2) continue;
        const int P = g_P[c];
        if (P > PMAX_SMEM) continue;

        float* seg = buf + (size_t)g_off[c] * DIMS + (size_t)d * P;

        for (int idx = tid; idx < P; idx += SORT_T)
            sh[idx] = (idx < m) ? seg[idx] : BIGF;
        __syncthreads();

        // phase 1: k = 2 .. min(32, P) in registers, chunked
        const int kmax1 = (P < 32) ? P : 32;
        for (int base = 0; base < P; base += SORT_T * SORT_VC) {
            float v[SORT_VC];
            #pragma unroll
            for (int w = 0; w < SORT_VC; w++) {
                int idx = base + w * SORT_T + tid;
                v[w] = (idx < P) ? sh[idx] : BIGF;
            }
            for (int k = 2; k <= kmax1; k <<= 1) {
                for (int j = k >> 1; j > 0; j >>= 1) {
                    #pragma unroll
                    for (int w = 0; w < SORT_VC; w++) {
                        int idx = base + w * SORT_T + tid;
                        float pv = __shfl_xor_sync(0xffffffffu, v[w], j);
                        bool desc  = (idx & k) != 0;
                        bool upper = (idx & j) != 0;
                        v[w] = (upper != desc) ? fmaxf(v[w], pv) : fminf(v[w], pv);
                    }
                }
            }
            #pragma unroll
            for (int w = 0; w < SORT_VC; w++) {
                int idx = base + w * SORT_T + tid;
                if (idx < P) sh[idx] = v[w];
            }
        }
        __syncthreads();

        // phase 2: k = 64 .. P; strides >=32 via shared, <=16 via registers
        for (int k = 64; k <= P; k <<= 1) {
            for (int j = k >> 1; j >= 32; j >>= 1) {
                for (int idx = tid; idx < P; idx += SORT_T) {
                    int l = idx ^ j;
                    if (l > idx) {
                        float a = sh[idx], b = sh[l];
                        bool up = ((idx & k) == 0);
                        if ((a > b) == up) { sh[idx] = b; sh[l] = a; }
                    }
                }
                __syncthreads();
            }
            for (int base = 0; base < P; base += SORT_T * SORT_VC) {
                float v[SORT_VC];
                #pragma unroll
                for (int w = 0; w < SORT_VC; w++) {
                    int idx = base + w * SORT_T + tid;
                    v[w] = (idx < P) ? sh[idx] : BIGF;
                }
                for (int j = 16; j > 0; j >>= 1) {
                    #pragma unroll
                    for (int w = 0; w < SORT_VC; w++) {
                        int idx = base + w * SORT_T + tid;
                        float pv = __shfl_xor_sync(0xffffffffu, v[w], j);
                        bool desc  = (idx & k) != 0;
                        bool upper = (idx & j) != 0;
                        v[w] = (upper != desc) ? fmaxf(v[w], pv) : fminf(v[w], pv);
                    }
                }
                #pragma unroll
                for (int w = 0; w < SORT_VC; w++) {
                    int idx = base + w * SORT_T + tid;
                    if (idx < P) sh[idx] = v[w];
                }
            }
            __syncthreads();
        }

        for (int idx = tid; idx < m; idx += SORT_T) seg[idx] = sh[idx];
        __syncthreads();
    }
}

// Fallback: grid-stride global-memory bitonic for P > PMAX_SMEM (rare)
__global__ void __launch_bounds__(1024)
k_sort_global() {
    const int T = blockDim.x, tid = threadIdx.x;
    for (int s = blockIdx.x; s < 2 * KD; s += gridDim.x) {
        float* buf = (s < KD) ? g_xg : g_tg;
        const int cd = (s < KD) ? s : s - KD;
        const int c = cd >> 6, d = cd & 63;
        const int m = g_m[c];
        if (m < 2) continue;
        const int P = g_P[c];
        if (P <= PMAX_SMEM) continue;

        float* seg = buf + (size_t)g_off[c] * DIMS + (size_t)d * P;
        for (int j = m + tid; j < P; j += T) seg[j] = BIGF;
        __syncthreads();

        for (int k = 2; k <= P; k <<= 1) {
            for (int j = k >> 1; j > 0; j >>= 1) {
                for (int idx = tid; idx < P; idx += T) {
                    int l = idx ^ j;
                    if (l > idx) {
                        float a = seg[idx], b = seg[l];
                        bool up = ((idx & k) == 0);
                        if ((a > b) == up) { seg[idx] = b; seg[l] = a; }
                    }
                }
                __syncthreads();
            }
        }
        __syncthreads();
    }
}

// ----------------------------------------------------------------------------
// K5: Wasserstein sums — one block per CLUSTER (128 atomics total, not 8192)
// ----------------------------------------------------------------------------
__global__ void k_diff() {
    const int c = blockIdx.x;
    const int m = g_m[c];
    if (m < 1) return;
    const int P = g_P[c];
    const size_t cbase = (size_t)g_off[c] * DIMS;
    const int total = DIMS * m;

    float s = 0.0f;
    for (int t = threadIdx.x; t < total; t += blockDim.x) {
        const int d = t / m, j = t - d * m;
        const size_t idx = cbase + (size_t)d * P + j;
        s += fabsf(g_xg[idx] - g_tg[idx]);
    }

    __shared__ float red[256];
    red[threadIdx.x] = s;
    __syncthreads();
    for (int o = blockDim.x >> 1; o > 0; o >>= 1) {
        if (threadIdx.x < o) red[threadIdx.x] += red[threadIdx.x + o];
        __syncthreads();
    }
    if (threadIdx.x == 0)
        atomicAdd(&g_loss[1], (double)red[0] / ((double)m * DIMS));
}

// ----------------------------------------------------------------------------
// K6: finalize
// ----------------------------------------------------------------------------
__global__ void k_final(float* out) {
    out[0] = (float)(g_loss[0] + g_loss[1]);
}

// ----------------------------------------------------------------------------
// Launch
// ----------------------------------------------------------------------------
extern "C" void kernel_launch(void* const* d_in, const int* in_sizes, int n_in,
                              void* d_out, int out_size) {
    const float* x     = (const float*)d_in[0];
    const float* tgt   = (const float*)d_in[1];
    const float* cc    = (const float*)d_in[2];
    const int*   predt = (const int*)d_in[3];
    const float* ftgt  = (const float*)d_in[4];
    float* out = (float*)d_out;

    const int ASSIGN_SMEM = (KCL * DIMS + KCL + KCL * ABLK + KCL) * 4 + KCL * 8;
    cudaFuncSetAttribute(k_assign,
                         cudaFuncAttributeMaxDynamicSharedMemorySize, ASSIGN_SMEM);
    cudaFuncSetAttribute(k_sort_ws,
                         cudaFuncAttributeMaxDynamicSharedMemorySize,
                         PMAX_SMEM * (int)sizeof(float));

    k_init<<<1, 128>>>();
    k_assign<<<NBLK, ABLK, ASSIGN_SMEM>>>(x, cc, predt);
    k_scan1<<<KCL, NBLK>>>();
    k_scan2<<<1, KCL>>>(ftgt);
    k_scatter2<<<NBLK, ABLK>>>(x, tgt, predt);
    k_sort_ws<<<1024, SORT_T, PMAX_SMEM * sizeof(float)>>>();   // launch idx 5 -> ncu
    k_sort_global<<<128, 1024>>>();
    k_diff<<<KCL, 256>>>();
    k_final<<<1, 1>>>(out);
}

// round 5
// speedup vs baseline: 1.5004x; 1.5004x over previous
#include <cuda_runtime.h>
#include <math.h>
#include <stdint.h>

#define N_PTS 65536
#define DIMS  64
#define KCL   128
#define ABLK  128                 // points per assign/scatter block
#define NBLK  (N_PTS / ABLK)      // 512
#define KD    (KCL * DIMS)        // 8192
#define EPSV  1e-8f
#define BIGF  3.402823466e38f
#define P_T1  4096                // tier-1 sort bound (16KB smem)
#define P_T2  32768               // tier-2 sort bound (128KB smem)

// ----------------------------------------------------------------------------
// Device scratch (static, no allocation)
// ----------------------------------------------------------------------------
__device__ int    g_pred[N_PTS];
__device__ int    g_histx[NBLK * KCL];
__device__ int    g_histt[NBLK * KCL];
__device__ float  g_fill[KCL];
__device__ int    g_m[KCL];
__device__ int    g_P[KCL];
__device__ int    g_off[KCL];
__device__ float  g_part[KD];     // per-(cluster,dim) Wasserstein partials
__device__ float  g_xg[(size_t)(2 * N_PTS) * DIMS];
__device__ float  g_tg[(size_t)(2 * N_PTS) * DIMS];

// ----------------------------------------------------------------------------
// K0: zero accumulators
// ----------------------------------------------------------------------------
__global__ void k_init() {
    int t = threadIdx.x;
    if (t < KCL) g_fill[t] = 0.0f;
}

// ----------------------------------------------------------------------------
// K1: distances to 128 centers, argmin, soft filling, per-block histograms.
// ----------------------------------------------------------------------------
__global__ void k_assign(const float* __restrict__ x, const float* __restrict__ cc,
                         const int* __restrict__ predt) {
    extern __shared__ float dyn[];
    float* sc    = dyn;                      // 8192
    float* scn   = sc + KCL * DIMS;          // 128
    float* wca   = scn + KCL;                // 16384
    float* sfill = wca + KCL * ABLK;         // 128
    int*   shx   = (int*)(sfill + KCL);      // 128
    int*   sht   = shx + KCL;                // 128

    const int tid = threadIdx.x;

    for (int j = tid; j < KCL * DIMS; j += ABLK) sc[j] = cc[j];
    if (tid < KCL) { sfill[tid] = 0.0f; shx[tid] = 0; sht[tid] = 0; }
    __syncthreads();
    if (tid < KCL) {
        float s = 0.0f;
        const float* cp = sc + tid * DIMS;
        #pragma unroll
        for (int d = 0; d < DIMS; d++) s += cp[d] * cp[d];
        scn[tid] = s;
    }
    __syncthreads();

    const int i = blockIdx.x * ABLK + tid;
    float xr[DIMS];
    {
        const float4* xp = (const float4*)(x + (size_t)i * DIMS);
        #pragma unroll
        for (int q = 0; q < 16; q++) {
            float4 v = xp[q];
            xr[4*q] = v.x; xr[4*q+1] = v.y; xr[4*q+2] = v.z; xr[4*q+3] = v.w;
        }
    }
    float xn = 0.0f;
    #pragma unroll
    for (int d = 0; d < DIMS; d++) xn += xr[d] * xr[d];

    float wsum = 0.0f, best = BIGF;
    int bc = 0;
    for (int c = 0; c < KCL; c++) {
        const float4* cp = (const float4*)(sc + c * DIMS);
        float a0 = 0.f, a1 = 0.f, a2 = 0.f, a3 = 0.f;
        #pragma unroll
        for (int q = 0; q < 16; q++) {
            float4 v = cp[q];
            a0 += xr[4*q]   * v.x;
            a1 += xr[4*q+1] * v.y;
            a2 += xr[4*q+2] * v.z;
            a3 += xr[4*q+3] * v.w;
        }
        float dot = (a0 + a1) + (a2 + a3);
        float d2 = xn + scn[c] - 2.0f * dot;
        float dist = sqrtf(fmaxf(d2, 0.0f));
        if (dist < best) { best = dist; bc = c; }
        float w = __fdividef(1.0f, dist + EPSV);
        wca[c * ABLK + tid] = w;
        wsum += w;
    }
    const float inv = __fdividef(1.0f, wsum);
    const int lane = tid & 31;

    for (int c = 0; c < KCL; c++) {
        float w = wca[c * ABLK + tid] * inv;
        #pragma unroll
        for (int o = 16; o > 0; o >>= 1) w += __shfl_down_sync(0xffffffffu, w, o);
        if (lane == 0) atomicAdd(&sfill[c], w);
    }

    g_pred[i] = bc;
    atomicAdd(&shx[bc], 1);
    atomicAdd(&sht[predt[i]], 1);
    __syncthreads();
    if (tid < KCL) {
        atomicAdd(&g_fill[tid], sfill[tid]);
        g_histx[blockIdx.x * KCL + tid] = shx[tid];
        g_histt[blockIdx.x * KCL + tid] = sht[tid];
    }
}

// ----------------------------------------------------------------------------
// K2: per-cluster exclusive scan of block histograms + m, P.
// ----------------------------------------------------------------------------
__global__ void k_scan1() {
    const int c = blockIdx.x;
    const int t = threadIdx.x;
    __shared__ int s[NBLK];

    int v = g_histx[t * KCL + c];
    s[t] = v; __syncthreads();
    int acc = v;
    for (int o = 1; o < NBLK; o <<= 1) {
        int add = (t >= o) ? s[t - o] : 0;
        __syncthreads();
        acc += add; s[t] = acc;
        __syncthreads();
    }
    g_histx[t * KCL + c] = acc - v;
    int cntx = s[NBLK - 1];
    __syncthreads();

    v = g_histt[t * KCL + c];
    s[t] = v; __syncthreads();
    acc = v;
    for (int o = 1; o < NBLK; o <<= 1) {
        int add = (t >= o) ? s[t - o] : 0;
        __syncthreads();
        acc += add; s[t] = acc;
        __syncthreads();
    }
    g_histt[t * KCL + c] = acc - v;
    int cntt = s[NBLK - 1];

    if (t == 0) {
        int m = min(cntx, cntt);
        g_m[c] = m;
        int P = 0;
        if (m > 0) { P = 1; while (P < m) P <<= 1; }
        g_P[c] = P;
    }
}

// ----------------------------------------------------------------------------
// K3: stable rank + gather both sides. Each block computes the cluster offsets
//     locally (identical values) and publishes g_off (benign identical writes).
//     *** placed at capture launch index 3 so ncu profiles it ***
// ----------------------------------------------------------------------------
__global__ void k_scatter2(const float* __restrict__ x, const float* __restrict__ tgt,
                           const int* __restrict__ predt) {
    __shared__ int cntx[KCL];
    __shared__ int cntt[KCL];
    __shared__ int soff[KCL];
    const int tid = threadIdx.x;
    if (tid < KCL) { cntx[tid] = 0; cntt[tid] = 0; }
    __syncthreads();

    // in-block exclusive prefix of g_P (Hillis-Steele over 128 lanes)
    if (tid < KCL) {
        int p = g_P[tid];
        soff[tid] = p;
    }
    __syncthreads();
    if (tid < KCL) {
        int acc = soff[tid];
        for (int o = 1; o < KCL; o <<= 1) {
            int add = (tid >= o) ? soff[tid - o] : 0;
            __syncthreads();
            acc += add; soff[tid] = acc;
            __syncthreads();
        }
        soff[tid] = acc - g_P[tid];   // exclusive
        g_off[tid] = soff[tid];       // publish (identical across blocks)
    }
    __syncthreads();

    const int i = blockIdx.x * ABLK + tid;
    const int cx = g_pred[i];
    const int ct = predt[i];
    const int myw = tid >> 5, lane = tid & 31;
    int rx = 0, rt = 0;

    for (int w = 0; w < ABLK / 32; w++) {
        if (myw == w) {
            unsigned peers = __match_any_sync(0xffffffffu, cx);
            unsigned lower = peers & ((1u << lane) - 1u);
            int leader = __ffs(peers) - 1;
            int base = 0;
            if (lane == leader) base = atomicAdd(&cntx[cx], __popc(peers));
            base = __shfl_sync(0xffffffffu, base, leader);
            rx = base + __popc(lower);

            peers = __match_any_sync(0xffffffffu, ct);
            lower = peers & ((1u << lane) - 1u);
            leader = __ffs(peers) - 1;
            base = 0;
            if (lane == leader) base = atomicAdd(&cntt[ct], __popc(peers));
            base = __shfl_sync(0xffffffffu, base, leader);
            rt = base + __popc(lower);
        }
        __syncthreads();
    }

    {
        const int r = g_histx[blockIdx.x * KCL + cx] + rx;
        if (r < g_m[cx]) {
            const int P = g_P[cx];
            float* dst = g_xg + (size_t)soff[cx] * DIMS + r;
            const float4* sp = (const float4*)(x + (size_t)i * DIMS);
            #pragma unroll
            for (int q = 0; q < 16; q++) {
                float4 v = sp[q];
                dst[(size_t)(4*q)     * P] = v.x;
                dst[(size_t)(4*q + 1) * P] = v.y;
                dst[(size_t)(4*q + 2) * P] = v.z;
                dst[(size_t)(4*q + 3) * P] = v.w;
            }
        }
    }
    {
        const int r = g_histt[blockIdx.x * KCL + ct] + rt;
        if (r < g_m[ct]) {
            const int P = g_P[ct];
            float* dst = g_tg + (size_t)soff[ct] * DIMS + r;
            const float4* sp = (const float4*)(tgt + (size_t)i * DIMS);
            #pragma unroll
            for (int q = 0; q < 16; q++) {
                float4 v = sp[q];
                dst[(size_t)(4*q)     * P] = v.x;
                dst[(size_t)(4*q + 1) * P] = v.y;
                dst[(size_t)(4*q + 2) * P] = v.z;
                dst[(size_t)(4*q + 3) * P] = v.w;
            }
        }
    }
}

// ----------------------------------------------------------------------------
// Shared bitonic sort body (register phases for strides <=16).
// ----------------------------------------------------------------------------
template<int TT, int VC>
__device__ __forceinline__ void sort_segment(float* sh, float* seg, int m, int P) {
    const int tid = threadIdx.x;

    for (int idx = tid; idx < P; idx += TT)
        sh[idx] = (idx < m) ? seg[idx] : BIGF;
    __syncthreads();

    const int kmax1 = (P < 32) ? P : 32;
    for (int base = 0; base < P; base += TT * VC) {
        float v[VC];
        #pragma unroll
        for (int w = 0; w < VC; w++) {
            int idx = base + w * TT + tid;
            v[w] = (idx < P) ? sh[idx] : BIGF;
        }
        for (int k = 2; k <= kmax1; k <<= 1) {
            for (int j = k >> 1; j > 0; j >>= 1) {
                #pragma unroll
                for (int w = 0; w < VC; w++) {
                    int idx = base + w * TT + tid;
                    float pv = __shfl_xor_sync(0xffffffffu, v[w], j);
                    bool desc  = (idx & k) != 0;
                    bool upper = (idx & j) != 0;
                    v[w] = (upper != desc) ? fmaxf(v[w], pv) : fminf(v[w], pv);
                }
            }
        }
        #pragma unroll
        for (int w = 0; w < VC; w++) {
            int idx = base + w * TT + tid;
            if (idx < P) sh[idx] = v[w];
        }
    }
    __syncthreads();

    for (int k = 64; k <= P; k <<= 1) {
        for (int j = k >> 1; j >= 32; j >>= 1) {
            for (int idx = tid; idx < P; idx += TT) {
                int l = idx ^ j;
                if (l > idx) {
                    float a = sh[idx], b = sh[l];
                    bool up = ((idx & k) == 0);
                    if ((a > b) == up) { sh[idx] = b; sh[l] = a; }
                }
            }
            __syncthreads();
        }
        for (int base = 0; base < P; base += TT * VC) {
            float v[VC];
            #pragma unroll
            for (int w = 0; w < VC; w++) {
                int idx = base + w * TT + tid;
                v[w] = (idx < P) ? sh[idx] : BIGF;
            }
            for (int j = 16; j > 0; j >>= 1) {
                #pragma unroll
                for (int w = 0; w < VC; w++) {
                    int idx = base + w * TT + tid;
                    float pv = __shfl_xor_sync(0xffffffffu, v[w], j);
                    bool desc  = (idx & k) != 0;
                    bool upper = (idx & j) != 0;
                    v[w] = (upper != desc) ? fmaxf(v[w], pv) : fminf(v[w], pv);
                }
            }
            #pragma unroll
            for (int w = 0; w < VC; w++) {
                int idx = base + w * TT + tid;
                if (idx < P) sh[idx] = v[w];
            }
        }
        __syncthreads();
    }

    for (int idx = tid; idx < m; idx += TT) seg[idx] = sh[idx];
}

// Tier 1: one block per segment, P <= P_T1 (16KB smem, high occupancy)
__global__ void __launch_bounds__(256)
k_sort_t1() {
    const int s = blockIdx.x;
    float* buf = (s < KD) ? g_xg : g_tg;
    const int cd = (s < KD) ? s : s - KD;
    const int c = cd >> 6, d = cd & 63;
    const int m = g_m[c];
    if (m < 2) return;
    const int P = g_P[c];
    if (P > P_T1) return;

    extern __shared__ float sh[];
    float* seg = buf + (size_t)g_off[c] * DIMS + (size_t)d * P;
    sort_segment<256, 8>(sh, seg, m, P);
}

// Tier 2: small grid-stride, P_T1 < P <= P_T2 (128KB smem, 512 threads)
__global__ void __launch_bounds__(512)
k_sort_t2() {
    extern __shared__ float sh[];
    for (int s = blockIdx.x; s < 2 * KD; s += gridDim.x) {
        float* buf = (s < KD) ? g_xg : g_tg;
        const int cd = (s < KD) ? s : s - KD;
        const int c = cd >> 6, d = cd & 63;
        const int m = g_m[c];
        if (m < 2) continue;
        const int P = g_P[c];
        if (P <= P_T1 || P > P_T2) continue;
        float* seg = buf + (size_t)g_off[c] * DIMS + (size_t)d * P;
        sort_segment<512, 8>(sh, seg, m, P);
        __syncthreads();
    }
}

// Tier 3: global-memory bitonic, P > P_T2 (degenerate giant cluster)
__global__ void __launch_bounds__(1024)
k_sort_t3() {
    const int T = blockDim.x, tid = threadIdx.x;
    for (int s = blockIdx.x; s < 2 * KD; s += gridDim.x) {
        float* buf = (s < KD) ? g_xg : g_tg;
        const int cd = (s < KD) ? s : s - KD;
        const int c = cd >> 6, d = cd & 63;
        const int m = g_m[c];
        if (m < 2) continue;
        const int P = g_P[c];
        if (P <= P_T2) continue;

        float* seg = buf + (size_t)g_off[c] * DIMS + (size_t)d * P;
        for (int j = m + tid; j < P; j += T) seg[j] = BIGF;
        __syncthreads();

        for (int k = 2; k <= P; k <<= 1) {
            for (int j = k >> 1; j > 0; j >>= 1) {
                for (int idx = tid; idx < P; idx += T) {
                    int l = idx ^ j;
                    if (l > idx) {
                        float a = seg[idx], b = seg[l];
                        bool up = ((idx & k) == 0);
                        if ((a > b) == up) { seg[idx] = b; seg[l] = a; }
                    }
                }
                __syncthreads();
            }
        }
        __syncthreads();
    }
}

// ----------------------------------------------------------------------------
// K5: Wasserstein partials per (cluster, dim) — NO contended atomics.
// ----------------------------------------------------------------------------
__global__ void k_diff() {
    const int cd = blockIdx.x;
    const int c = cd >> 6, d = cd & 63;
    const int m = g_m[c];
    if (m < 1) { if (threadIdx.x == 0) g_part[cd] = 0.0f; return; }
    const int P = g_P[c];
    const size_t base = (size_t)g_off[c] * DIMS + (size_t)d * P;

    float s = 0.0f;
    for (int j = threadIdx.x; j < m; j += blockDim.x)
        s += fabsf(g_xg[base + j] - g_tg[base + j]);

    __shared__ float red[256];
    red[threadIdx.x] = s;
    __syncthreads();
    for (int o = blockDim.x >> 1; o > 0; o >>= 1) {
        if (threadIdx.x < o) red[threadIdx.x] += red[threadIdx.x + o];
        __syncthreads();
    }
    if (threadIdx.x == 0)
        g_part[cd] = red[0] / ((float)m * DIMS);
}

// ----------------------------------------------------------------------------
// K6: finalize — loss_fil + sum of partials (deterministic single block)
// ----------------------------------------------------------------------------
__global__ void k_final(const float* __restrict__ ftgt, float* out) {
    const int tid = threadIdx.x;      // 256 threads
    __shared__ double red[256];

    double s = 0.0;
    for (int i = tid; i < KD; i += 256) s += (double)g_part[i];
    red[tid] = s;
    __syncthreads();
    for (int o = 128; o > 0; o >>= 1) {
        if (tid < o) red[tid] += red[tid + o];
        __syncthreads();
    }

    if (tid == 0) {
        float lf = 0.0f;
        for (int c = 0; c < KCL; c++) {
            float diff = g_fill[c] * (1.0f / N_PTS) - ftgt[c];
            lf += diff * diff;
        }
        out[0] = (float)((double)(lf / KCL) + red[0]);
    }
}

// ----------------------------------------------------------------------------
// Launch
// ----------------------------------------------------------------------------
extern "C" void kernel_launch(void* const* d_in, const int* in_sizes, int n_in,
                              void* d_out, int out_size) {
    const float* x     = (const float*)d_in[0];
    const float* tgt   = (const float*)d_in[1];
    const float* cc    = (const float*)d_in[2];
    const int*   predt = (const int*)d_in[3];
    const float* ftgt  = (const float*)d_in[4];
    float* out = (float*)d_out;

    const int ASSIGN_SMEM = (KCL * DIMS + KCL + KCL * ABLK + KCL) * 4 + KCL * 8;
    cudaFuncSetAttribute(k_assign,
                         cudaFuncAttributeMaxDynamicSharedMemorySize, ASSIGN_SMEM);
    cudaFuncSetAttribute(k_sort_t2,
                         cudaFuncAttributeMaxDynamicSharedMemorySize,
                         P_T2 * (int)sizeof(float));

    k_init<<<1, 128>>>();                                      // 0
    k_assign<<<NBLK, ABLK, ASSIGN_SMEM>>>(x, cc, predt);       // 1
    k_scan1<<<KCL, NBLK>>>();                                  // 2
    k_scatter2<<<NBLK, ABLK>>>(x, tgt, predt);                 // 3 <- ncu
    k_sort_t1<<<2 * KD, 256, P_T1 * sizeof(float)>>>();        // 4
    k_sort_t2<<<1024, 512, P_T2 * sizeof(float)>>>();          // 5
    k_sort_t3<<<256, 1024>>>();                                // 6
    k_diff<<<KD, 256>>>();                                     // 7
    k_final<<<1, 256>>>(ftgt, out);                            // 8
}

// round 6
// speedup vs baseline: 1.7984x; 1.1987x over previous
#include <cuda_runtime.h>
#include <math.h>
#include <stdint.h>

#define N_PTS 65536
#define DIMS  64
#define KCL   128
#define ABLK  128                 // points per assign/scatter block
#define NBLK  (N_PTS / ABLK)      // 512
#define KD    (KCL * DIMS)        // 8192
#define EPSV  1e-8f
#define BIGF  3.402823466e38f
#define RT    512                 // radix threads
#define NW    (RT / 32)           // 16 warps
#define HALF  16384

// ----------------------------------------------------------------------------
// Device scratch (static, no allocation)
// ----------------------------------------------------------------------------
__device__ int    g_pred[N_PTS];
__device__ int    g_histx[NBLK * KCL];
__device__ int    g_histt[NBLK * KCL];
__device__ float  g_fillp[NBLK * KCL];   // per-block fill partials
__device__ float  g_fill[KCL];
__device__ int    g_m[KCL];
__device__ int    g_P[KCL];
__device__ int    g_off[KCL];
__device__ float  g_part[KD];            // per-(cluster,dim) Wasserstein partials
// compacted sort work lists (cluster ids) + counts
__device__ int    g_l1[KCL], g_l2a[KCL], g_l2b[KCL], g_l3[KCL];
__device__ int    g_n1, g_n2a, g_n2b, g_n3;
__device__ float  g_xg[(size_t)(2 * N_PTS) * DIMS];
__device__ float  g_tg[(size_t)(2 * N_PTS) * DIMS];

// ----------------------------------------------------------------------------
// K1: distances to 128 centers, argmin, soft filling, per-block histograms.
// ----------------------------------------------------------------------------
__global__ void k_assign(const float* __restrict__ x, const float* __restrict__ cc,
                         const int* __restrict__ predt) {
    extern __shared__ float dyn[];
    float* sc    = dyn;                      // 8192
    float* scn   = sc + KCL * DIMS;          // 128
    float* wca   = scn + KCL;                // 16384
    float* sfill = wca + KCL * ABLK;         // 128
    int*   shx   = (int*)(sfill + KCL);      // 128
    int*   sht   = shx + KCL;                // 128

    const int tid = threadIdx.x;

    for (int j = tid; j < KCL * DIMS; j += ABLK) sc[j] = cc[j];
    if (tid < KCL) { sfill[tid] = 0.0f; shx[tid] = 0; sht[tid] = 0; }
    __syncthreads();
    if (tid < KCL) {
        float s = 0.0f;
        const float* cp = sc + tid * DIMS;
        #pragma unroll
        for (int d = 0; d < DIMS; d++) s += cp[d] * cp[d];
        scn[tid] = s;
    }
    __syncthreads();

    const int i = blockIdx.x * ABLK + tid;
    float xr[DIMS];
    {
        const float4* xp = (const float4*)(x + (size_t)i * DIMS);
        #pragma unroll
        for (int q = 0; q < 16; q++) {
            float4 v = xp[q];
            xr[4*q] = v.x; xr[4*q+1] = v.y; xr[4*q+2] = v.z; xr[4*q+3] = v.w;
        }
    }
    float xn = 0.0f;
    #pragma unroll
    for (int d = 0; d < DIMS; d++) xn += xr[d] * xr[d];

    float wsum = 0.0f, best = BIGF;
    int bc = 0;
    for (int c = 0; c < KCL; c++) {
        const float4* cp = (const float4*)(sc + c * DIMS);
        float a0 = 0.f, a1 = 0.f, a2 = 0.f, a3 = 0.f;
        #pragma unroll
        for (int q = 0; q < 16; q++) {
            float4 v = cp[q];
            a0 += xr[4*q]   * v.x;
            a1 += xr[4*q+1] * v.y;
            a2 += xr[4*q+2] * v.z;
            a3 += xr[4*q+3] * v.w;
        }
        float dot = (a0 + a1) + (a2 + a3);
        float d2 = xn + scn[c] - 2.0f * dot;
        float dist = sqrtf(fmaxf(d2, 0.0f));
        if (dist < best) { best = dist; bc = c; }
        float w = __fdividef(1.0f, dist + EPSV);
        wca[c * ABLK + tid] = w;
        wsum += w;
    }
    const float inv = __fdividef(1.0f, wsum);
    const int lane = tid & 31;

    for (int c = 0; c < KCL; c++) {
        float w = wca[c * ABLK + tid] * inv;
        #pragma unroll
        for (int o = 16; o > 0; o >>= 1) w += __shfl_down_sync(0xffffffffu, w, o);
        if (lane == 0) atomicAdd(&sfill[c], w);
    }

    g_pred[i] = bc;
    atomicAdd(&shx[bc], 1);
    atomicAdd(&sht[predt[i]], 1);
    __syncthreads();
    if (tid < KCL) {
        g_fillp[blockIdx.x * KCL + tid] = sfill[tid];
        g_histx[blockIdx.x * KCL + tid] = shx[tid];
        g_histt[blockIdx.x * KCL + tid] = sht[tid];
    }
}

// ----------------------------------------------------------------------------
// K2: per-cluster scan of block hists + m, P + fill reduction.
// ----------------------------------------------------------------------------
__global__ void k_scan1() {
    const int c = blockIdx.x;
    const int t = threadIdx.x;
    __shared__ int   s[NBLK];
    __shared__ float sf[NBLK];

    int v = g_histx[t * KCL + c];
    s[t] = v; __syncthreads();
    int acc = v;
    for (int o = 1; o < NBLK; o <<= 1) {
        int add = (t >= o) ? s[t - o] : 0;
        __syncthreads();
        acc += add; s[t] = acc;
        __syncthreads();
    }
    g_histx[t * KCL + c] = acc - v;
    int cntx = s[NBLK - 1];
    __syncthreads();

    v = g_histt[t * KCL + c];
    s[t] = v; __syncthreads();
    acc = v;
    for (int o = 1; o < NBLK; o <<= 1) {
        int add = (t >= o) ? s[t - o] : 0;
        __syncthreads();
        acc += add; s[t] = acc;
        __syncthreads();
    }
    g_histt[t * KCL + c] = acc - v;
    int cntt = s[NBLK - 1];
    __syncthreads();

    sf[t] = g_fillp[t * KCL + c];
    __syncthreads();
    for (int o = NBLK / 2; o > 0; o >>= 1) {
        if (t < o) sf[t] += sf[t + o];
        __syncthreads();
    }

    if (t == 0) {
        g_fill[c] = sf[0];
        int m = min(cntx, cntt);
        g_m[c] = m;
        int P = 0;
        if (m > 0) { P = 1; while (P < m) P <<= 1; }
        g_P[c] = P;
    }
}

// ----------------------------------------------------------------------------
// K3: stable rank + gather both sides; also builds g_off and tier work lists
//     (all blocks compute identical values -> benign identical writes).
// ----------------------------------------------------------------------------
__global__ void k_scatter2(const float* __restrict__ x, const float* __restrict__ tgt,
                           const int* __restrict__ predt) {
    __shared__ int cntx[KCL];
    __shared__ int cntt[KCL];
    __shared__ int soff[KCL];
    __shared__ int f1[KCL], f2a[KCL], f2b[KCL], f3[KCL];
    const int tid = threadIdx.x;   // blockDim = 128 = KCL
    cntx[tid] = 0; cntt[tid] = 0;

    const int mC = g_m[tid];
    const int PC = g_P[tid];
    soff[tid] = PC;
    f1[tid]  = (mC >= 2 && PC <= 2048) ? 1 : 0;
    f2a[tid] = (PC == 4096 || PC == 8192) ? 1 : 0;
    f2b[tid] = (PC == 16384 || PC == 32768) ? 1 : 0;
    f3[tid]  = (PC > 32768) ? 1 : 0;
    __syncthreads();

    // 5 inclusive Hillis scans over 128 entries
    int aoff = soff[tid], a1 = f1[tid], a2a = f2a[tid], a2b = f2b[tid], a3 = f3[tid];
    for (int o = 1; o < KCL; o <<= 1) {
        int b0 = (tid >= o) ? soff[tid - o] : 0;
        int b1 = (tid >= o) ? f1[tid - o]  : 0;
        int b2 = (tid >= o) ? f2a[tid - o] : 0;
        int b3 = (tid >= o) ? f2b[tid - o] : 0;
        int b4 = (tid >= o) ? f3[tid - o]  : 0;
        __syncthreads();
        aoff += b0; a1 += b1; a2a += b2; a2b += b3; a3 += b4;
        soff[tid] = aoff; f1[tid] = a1; f2a[tid] = a2a; f2b[tid] = a2b; f3[tid] = a3;
        __syncthreads();
    }
    soff[tid] = aoff - PC;            // exclusive offsets
    g_off[tid] = soff[tid];
    if (mC >= 2 && PC <= 2048)            g_l1[a1 - 1]  = tid;
    if (PC == 4096 || PC == 8192)         g_l2a[a2a - 1] = tid;
    if (PC == 16384 || PC == 32768)       g_l2b[a2b - 1] = tid;
    if (PC > 32768)                       g_l3[a3 - 1]  = tid;
    if (tid == KCL - 1) { g_n1 = a1; g_n2a = a2a; g_n2b = a2b; g_n3 = a3; }
    __syncthreads();

    const int i = blockIdx.x * ABLK + tid;
    const int cx = g_pred[i];
    const int ct = predt[i];
    const int myw = tid >> 5, lane = tid & 31;
    int rx = 0, rt = 0;

    for (int w = 0; w < ABLK / 32; w++) {
        if (myw == w) {
            unsigned peers = __match_any_sync(0xffffffffu, cx);
            unsigned lower = peers & ((1u << lane) - 1u);
            int leader = __ffs(peers) - 1;
            int base = 0;
            if (lane == leader) base = atomicAdd(&cntx[cx], __popc(peers));
            base = __shfl_sync(0xffffffffu, base, leader);
            rx = base + __popc(lower);

            peers = __match_any_sync(0xffffffffu, ct);
            lower = peers & ((1u << lane) - 1u);
            leader = __ffs(peers) - 1;
            base = 0;
            if (lane == leader) base = atomicAdd(&cntt[ct], __popc(peers));
            base = __shfl_sync(0xffffffffu, base, leader);
            rt = base + __popc(lower);
        }
        __syncthreads();
    }

    {
        const int r = g_histx[blockIdx.x * KCL + cx] + rx;
        if (r < g_m[cx]) {
            const int P = g_P[cx];
            float* dst = g_xg + (size_t)soff[cx] * DIMS + r;
            const float4* sp = (const float4*)(x + (size_t)i * DIMS);
            #pragma unroll
            for (int q = 0; q < 16; q++) {
                float4 v = sp[q];
                dst[(size_t)(4*q)     * P] = v.x;
                dst[(size_t)(4*q + 1) * P] = v.y;
                dst[(size_t)(4*q + 2) * P] = v.z;
                dst[(size_t)(4*q + 3) * P] = v.w;
            }
        }
    }
    {
        const int r = g_histt[blockIdx.x * KCL + ct] + rt;
        if (r < g_m[ct]) {
            const int P = g_P[ct];
            float* dst = g_tg + (size_t)soff[ct] * DIMS + r;
            const float4* sp = (const float4*)(tgt + (size_t)i * DIMS);
            #pragma unroll
            for (int q = 0; q < 16; q++) {
                float4 v = sp[q];
                dst[(size_t)(4*q)     * P] = v.x;
                dst[(size_t)(4*q + 1) * P] = v.y;
                dst[(size_t)(4*q + 2) * P] = v.z;
                dst[(size_t)(4*q + 3) * P] = v.w;
            }
        }
    }
}

// ----------------------------------------------------------------------------
// Radix sort machinery (keys = order-preserving uint transform of float)
// ----------------------------------------------------------------------------
__device__ __forceinline__ unsigned f2k(float f) {
    unsigned b = __float_as_uint(f);
    return (b & 0x80000000u) ? ~b : (b | 0x80000000u);
}
__device__ __forceinline__ float k2f(unsigned k) {
    unsigned b = (k & 0x80000000u) ? (k & 0x7FFFFFFFu) : ~k;
    return __uint_as_float(b);
}

// one stable 8-bit pass src->dst (shared), n multiple of RT
__device__ void radix_pass(const unsigned* src, unsigned* dst, unsigned* hist,
                           unsigned* tot, int n, int shift) {
    const int tid = threadIdx.x, w = tid >> 5, l = tid & 31;
    const int E = n / RT;
    const int wbase = w * 32 * E;

    for (int i = tid; i < NW * 256; i += RT) hist[i] = 0;
    __syncthreads();

    for (int e = 0; e < E; e++) {
        unsigned u = src[wbase + e * 32 + l];
        atomicAdd(&hist[w * 256 + ((u >> shift) & 255u)], 1u);
    }
    __syncthreads();

    if (tid < 256) {                       // per-warp prefix + column totals
        unsigned run = 0;
        for (int ww = 0; ww < NW; ww++) {
            unsigned t = hist[ww * 256 + tid];
            hist[ww * 256 + tid] = run;
            run += t;
        }
        tot[tid] = run;
    }
    __syncthreads();

    unsigned orig = 0, acc = 0;            // exclusive scan of tot (all threads in barriers)
    if (tid < 256) { orig = tot[tid]; acc = orig; }
    for (int o = 1; o < 256; o <<= 1) {
        unsigned add = (tid >= o && tid < 256) ? tot[tid - o] : 0;
        __syncthreads();
        if (tid < 256) { acc += add; tot[tid] = acc; }
        __syncthreads();
    }
    if (tid < 256) tot[tid] = acc - orig;
    __syncthreads();

    for (int i = tid; i < NW * 256; i += RT) hist[i] += tot[i & 255];
    __syncthreads();

    for (int e = 0; e < E; e++) {          // stable scatter, processing = memory order
        unsigned u = src[wbase + e * 32 + l];
        unsigned d = (u >> shift) & 255u;
        unsigned peers = __match_any_sync(0xffffffffu, d);
        int leader = __ffs(peers) - 1;
        unsigned base = 0;
        if (l == leader) base = hist[w * 256 + d];
        base = __shfl_sync(0xffffffffu, base, leader);
        unsigned rank = base + __popc(peers & ((1u << l) - 1u));
        if (l == leader) hist[w * 256 + d] = base + __popc(peers);
        dst[rank] = u;
    }
    __syncthreads();
}

__device__ void radix_sort_n(unsigned* A, unsigned* PP, unsigned* hist,
                             unsigned* tot, int n) {
    radix_pass(A, PP, hist, tot, n, 0);
    radix_pass(PP, A, hist, tot, n, 8);
    radix_pass(A, PP, hist, tot, n, 16);
    radix_pass(PP, A, hist, tot, n, 24);
}

// merge two sorted 16K halves (shared) -> global floats
__device__ void merge_write(const unsigned* A, const unsigned* B, float* out) {
    const int tid = threadIdx.x;
    const int k0 = tid * (2 * HALF / RT);         // 64 outputs per thread
    int lo = max(0, k0 - HALF), hi = min(k0, HALF);
    while (lo < hi) {
        int mid = (lo + hi) >> 1;
        if (A[mid] <= B[k0 - mid - 1]) lo = mid + 1; else hi = mid;
    }
    int a = lo, b = k0 - lo;
    #pragma unroll 4
    for (int o = 0; o < 2 * HALF / RT; o++) {
        unsigned va = (a < HALF) ? A[a] : 0xFFFFFFFFu;
        unsigned vb = (b < HALF) ? B[b] : 0xFFFFFFFFu;
        unsigned v;
        if (va <= vb) { v = va; a++; } else { v = vb; b++; }
        out[k0 + o] = k2f(v);
    }
}

// Large radix: P in {16384, 32768}.  smem: R0|R1|R2|hist|tot
__global__ void __launch_bounds__(RT)
k_sort_radixL() {
    extern __shared__ unsigned su[];
    unsigned* R0 = su;
    unsigned* R1 = su + HALF;
    unsigned* R2 = su + 2 * HALF;
    unsigned* hist = su + 3 * HALF;
    unsigned* tot = hist + NW * 256;
    const int tid = threadIdx.x;
    const int nseg = g_n2b * 128;

    for (int s = blockIdx.x; s < nseg; s += gridDim.x) {
        const int c = g_l2b[s >> 7];
        const int r = s & 127;
        const int d = r & 63;
        const int m = g_m[c], P = g_P[c];
        float* seg = ((r >> 6) ? g_tg : g_xg) + (size_t)g_off[c] * DIMS + (size_t)d * P;

        if (P <= HALF) {
            for (int i = tid; i < P; i += RT)
                R0[i] = (i < m) ? f2k(seg[i]) : 0xFFFFFFFFu;
            __syncthreads();
            radix_sort_n(R0, R2, hist, tot, P);
            for (int i = tid; i < m; i += RT) seg[i] = k2f(R0[i]);
        } else {  // P == 32768
            for (int i = tid; i < HALF; i += RT)
                R0[i] = (i < m) ? f2k(seg[i]) : 0xFFFFFFFFu;
            __syncthreads();
            radix_sort_n(R0, R2, hist, tot, HALF);
            for (int i = tid; i < HALF; i += RT) {
                int j = HALF + i;
                R1[i] = (j < m) ? f2k(seg[j]) : 0xFFFFFFFFu;
            }
            __syncthreads();
            radix_sort_n(R1, R2, hist, tot, HALF);
            merge_write(R0, R1, seg);
        }
        __syncthreads();
    }
}

// Small radix: P in {4096, 8192}.  smem: R0(8192)|R2(8192)|hist|tot
__global__ void __launch_bounds__(RT)
k_sort_radixS() {
    extern __shared__ unsigned su[];
    unsigned* R0 = su;
    unsigned* R2 = su + 8192;
    unsigned* hist = su + 16384;
    unsigned* tot = hist + NW * 256;
    const int tid = threadIdx.x;
    const int nseg = g_n2a * 128;

    for (int s = blockIdx.x; s < nseg; s += gridDim.x) {
        const int c = g_l2a[s >> 7];
        const int r = s & 127;
        const int d = r & 63;
        const int m = g_m[c], P = g_P[c];
        float* seg = ((r >> 6) ? g_tg : g_xg) + (size_t)g_off[c] * DIMS + (size_t)d * P;

        for (int i = tid; i < P; i += RT)
            R0[i] = (i < m) ? f2k(seg[i]) : 0xFFFFFFFFu;
        __syncthreads();
        radix_sort_n(R0, R2, hist, tot, P);
        for (int i = tid; i < m; i += RT) seg[i] = k2f(R0[i]);
        __syncthreads();
    }
}

// ----------------------------------------------------------------------------
// Bitonic for small P (<=2048), register/shfl phases for strides <=16.
// ----------------------------------------------------------------------------
template<int TT, int VC>
__device__ __forceinline__ void sort_segment(float* sh, float* seg, int m, int P) {
    const int tid = threadIdx.x;

    for (int idx = tid; idx < P; idx += TT)
        sh[idx] = (idx < m) ? seg[idx] : BIGF;
    __syncthreads();

    const int kmax1 = (P < 32) ? P : 32;
    for (int base = 0; base < P; base += TT * VC) {
        float v[VC];
        #pragma unroll
        for (int w = 0; w < VC; w++) {
            int idx = base + w * TT + tid;
            v[w] = (idx < P) ? sh[idx] : BIGF;
        }
        for (int k = 2; k <= kmax1; k <<= 1) {
            for (int j = k >> 1; j > 0; j >>= 1) {
                #pragma unroll
                for (int w = 0; w < VC; w++) {
                    int idx = base + w * TT + tid;
                    float pv = __shfl_xor_sync(0xffffffffu, v[w], j);
                    bool desc  = (idx & k) != 0;
                    bool upper = (idx & j) != 0;
                    v[w] = (upper != desc) ? fmaxf(v[w], pv) : fminf(v[w], pv);
                }
            }
        }
        #pragma unroll
        for (int w = 0; w < VC; w++) {
            int idx = base + w * TT + tid;
            if (idx < P) sh[idx] = v[w];
        }
    }
    __syncthreads();

    for (int k = 64; k <= P; k <<= 1) {
        for (int j = k >> 1; j >= 32; j >>= 1) {
            for (int idx = tid; idx < P; idx += TT) {
                int l = idx ^ j;
                if (l > idx) {
                    float a = sh[idx], b = sh[l];
                    bool up = ((idx & k) == 0);
                    if ((a > b) == up) { sh[idx] = b; sh[l] = a; }
                }
            }
            __syncthreads();
        }
        for (int base = 0; base < P; base += TT * VC) {
            float v[VC];
            #pragma unroll
            for (int w = 0; w < VC; w++) {
                int idx = base + w * TT + tid;
                v[w] = (idx < P) ? sh[idx] : BIGF;
            }
            for (int j = 16; j > 0; j >>= 1) {
                #pragma unroll
                for (int w = 0; w < VC; w++) {
                    int idx = base + w * TT + tid;
                    float pv = __shfl_xor_sync(0xffffffffu, v[w], j);
                    bool desc  = (idx & k) != 0;
                    bool upper = (idx & j) != 0;
                    v[w] = (upper != desc) ? fmaxf(v[w], pv) : fminf(v[w], pv);
                }
            }
            #pragma unroll
            for (int w = 0; w < VC; w++) {
                int idx = base + w * TT + tid;
                if (idx < P) sh[idx] = v[w];
            }
        }
        __syncthreads();
    }

    for (int idx = tid; idx < m; idx += TT) seg[idx] = sh[idx];
}

__global__ void __launch_bounds__(256)
k_sort_t1() {
    extern __shared__ float sh[];
    const int nseg = g_n1 * 128;
    for (int s = blockIdx.x; s < nseg; s += gridDim.x) {
        const int c = g_l1[s >> 7];
        const int r = s & 127;
        const int d = r & 63;
        const int m = g_m[c], P = g_P[c];
        float* seg = ((r >> 6) ? g_tg : g_xg) + (size_t)g_off[c] * DIMS + (size_t)d * P;
        sort_segment<256, 8>(sh, seg, m, P);
        __syncthreads();
    }
}

// Global bitonic fallback, P > 32768 (not expected)
__global__ void __launch_bounds__(1024)
k_sort_t3() {
    const int T = blockDim.x, tid = threadIdx.x;
    const int nseg = g_n3 * 128;
    for (int s = blockIdx.x; s < nseg; s += gridDim.x) {
        const int c = g_l3[s >> 7];
        const int r = s & 127;
        const int d = r & 63;
        const int m = g_m[c], P = g_P[c];
        float* seg = ((r >> 6) ? g_tg : g_xg) + (size_t)g_off[c] * DIMS + (size_t)d * P;
        for (int j = m + tid; j < P; j += T) seg[j] = BIGF;
        __syncthreads();
        for (int k = 2; k <= P; k <<= 1) {
            for (int j = k >> 1; j > 0; j >>= 1) {
                for (int idx = tid; idx < P; idx += T) {
                    int l = idx ^ j;
                    if (l > idx) {
                        float a = seg[idx], b = seg[l];
                        bool up = ((idx & k) == 0);
                        if ((a > b) == up) { seg[idx] = b; seg[l] = a; }
                    }
                }
                __syncthreads();
            }
        }
        __syncthreads();
    }
}

// ----------------------------------------------------------------------------
// K5: Wasserstein partials per (cluster, dim)
// ----------------------------------------------------------------------------
__global__ void k_diff() {
    const int cd = blockIdx.x;
    const int c = cd >> 6, d = cd & 63;
    const int m = g_m[c];
    if (m < 1) { if (threadIdx.x == 0) g_part[cd] = 0.0f; return; }
    const int P = g_P[c];
    const size_t base = (size_t)g_off[c] * DIMS + (size_t)d * P;

    float s = 0.0f;
    for (int j = threadIdx.x; j < m; j += blockDim.x)
        s += fabsf(g_xg[base + j] - g_tg[base + j]);

    __shared__ float red[256];
    red[threadIdx.x] = s;
    __syncthreads();
    for (int o = blockDim.x >> 1; o > 0; o >>= 1) {
        if (threadIdx.x < o) red[threadIdx.x] += red[threadIdx.x + o];
        __syncthreads();
    }
    if (threadIdx.x == 0)
        g_part[cd] = red[0] / ((float)m * DIMS);
}

// ----------------------------------------------------------------------------
// K6: finalize
// ----------------------------------------------------------------------------
__global__ void k_final(const float* __restrict__ ftgt, float* out) {
    const int tid = threadIdx.x;
    __shared__ double red[256];

    double s = 0.0;
    for (int i = tid; i < KD; i += 256) s += (double)g_part[i];
    red[tid] = s;
    __syncthreads();
    for (int o = 128; o > 0; o >>= 1) {
        if (tid < o) red[tid] += red[tid + o];
        __syncthreads();
    }

    if (tid == 0) {
        float lf = 0.0f;
        for (int c = 0; c < KCL; c++) {
            float diff = g_fill[c] * (1.0f / N_PTS) - ftgt[c];
            lf += diff * diff;
        }
        out[0] = (float)((double)(lf / KCL) + red[0]);
    }
}

// ----------------------------------------------------------------------------
// Launch
// ----------------------------------------------------------------------------
extern "C" void kernel_launch(void* const* d_in, const int* in_sizes, int n_in,
                              void* d_out, int out_size) {
    const float* x     = (const float*)d_in[0];
    const float* tgt   = (const float*)d_in[1];
    const float* cc    = (const float*)d_in[2];
    const int*   predt = (const int*)d_in[3];
    const float* ftgt  = (const float*)d_in[4];
    float* out = (float*)d_out;

    const int ASSIGN_SMEM = (KCL * DIMS + KCL + KCL * ABLK + KCL) * 4 + KCL * 8;
    const int RADL_SMEM = (3 * HALF + NW * 256 + 256) * 4;   // 214016 B
    const int RADS_SMEM = (2 * 8192 + NW * 256 + 256) * 4;   // 82944 B
    cudaFuncSetAttribute(k_assign,
                         cudaFuncAttributeMaxDynamicSharedMemorySize, ASSIGN_SMEM);
    cudaFuncSetAttribute(k_sort_radixL,
                         cudaFuncAttributeMaxDynamicSharedMemorySize, RADL_SMEM);
    cudaFuncSetAttribute(k_sort_radixS,
                         cudaFuncAttributeMaxDynamicSharedMemorySize, RADS_SMEM);

    k_assign<<<NBLK, ABLK, ASSIGN_SMEM>>>(x, cc, predt);     // 0
    k_scan1<<<KCL, NBLK>>>();                                // 1
    k_scatter2<<<NBLK, ABLK>>>(x, tgt, predt);               // 2
    k_sort_radixL<<<148, RT, RADL_SMEM>>>();                 // 3 <- ncu
    k_sort_radixS<<<296, RT, RADS_SMEM>>>();                 // 4
    k_sort_t1<<<2048, 256, 2048 * sizeof(float)>>>();        // 5
    k_sort_t3<<<148, 1024>>>();                              // 6
    k_diff<<<KD, 256>>>();                                   // 7
    k_final<<<1, 256>>>(ftgt, out);                          // 8
}